// round 1
// baseline (speedup 1.0000x reference)
#include <cuda_runtime.h>
#include <cuda_bf16.h>
#include <cstdint>
#include <cstddef>

// ---------------------------------------------------------------------------
// GraphConv: bipartite GNN layer.
//   mv = seg_sum(fmv_pos(hc)[pos_c] -> pos_v) + seg_sum(fmv_neg(hc)[neg_c] -> neg_v)
//   mc = seg_sum(fmc_pos(hv)[pos_v] -> pos_c) + seg_sum(fmc_neg(hv)[neg_v] -> neg_c)
//   hv_out = mlp2([hv|mv], fuv)   hc_out = mlp2([hc|mc], fuc)
// All fp32 this round (establish correct baseline; tensor cores next).
// ---------------------------------------------------------------------------

#define D128 128
#define NV_MAX 100000
#define NC_MAX 400000
#define TM 64   // rows per CTA in the MLP kernel

// Scratch (static __device__ arrays per allocation rules)
__device__ float g_tmpA[(size_t)NC_MAX * D128];  // fmv_pos(hc)
__device__ float g_tmpB[(size_t)NC_MAX * D128];  // fmv_neg(hc)
__device__ float g_tmpC[(size_t)NV_MAX * D128];  // fmc_pos(hv)
__device__ float g_tmpD[(size_t)NV_MAX * D128];  // fmc_neg(hv)
__device__ float g_mv[(size_t)NV_MAX * D128];
__device__ float g_mc[(size_t)NC_MAX * D128];

// ---------------------------------------------------------------------------
// Fused 2-layer MLP: out = relu(relu(x @ W1 + b1) @ W2 + b2)
// KIN = 128 (x = x0) or 256 (x = [x0 | x1] concat).
// npass = 2 runs a second parameter set (b-suffixed) against the SAME x tile
// (used for the pos/neg message MLP pair -> x loaded once).
//
// Block: 256 threads, TM=64 rows. Thread (tx=tid&15, ty=tid>>4) computes a
// 4-row x 8-col microtile of the 64x128 output.
// Smem: sX [TM][KIN+4] (padded), sH [TM][132], sW [128][128] (reused for W1
// chunks and W2).
// ---------------------------------------------------------------------------
template <int KIN>
__global__ void __launch_bounds__(256, 1)
mlp2_kernel(const float* __restrict__ x0, const float* __restrict__ x1,
            const float* __restrict__ W1a, const float* __restrict__ b1a,
            const float* __restrict__ W2a, const float* __restrict__ b2a,
            float* __restrict__ outA,
            const float* __restrict__ W1b, const float* __restrict__ b1b,
            const float* __restrict__ W2b, const float* __restrict__ b2b,
            float* __restrict__ outB,
            int nrows, int npass)
{
    extern __shared__ float smem[];
    constexpr int XS = KIN + 4;   // padded x stride (floats)
    constexpr int HS = 132;       // padded h stride
    float* sX = smem;                    // TM * XS
    float* sH = sX + TM * XS;            // TM * HS
    float* sW = sH + TM * HS;            // 128 * 128

    const int tid = threadIdx.x;
    const int tx = tid & 15;             // col group: cols [tx*8, tx*8+8)
    const int ty = tid >> 4;             // row group: rows [ty*4, ty*4+4)
    const int row0 = blockIdx.x * TM;

    // ---- load x tile (zero-fill OOB rows) ----
    constexpr int KV = KIN / 4;          // float4s per row
    for (int i = tid; i < TM * KV; i += 256) {
        const int r  = i / KV;
        const int kv = i % KV;
        const int gr = row0 + r;
        float4 v = make_float4(0.f, 0.f, 0.f, 0.f);
        if (gr < nrows) {
            if (KIN == 256) {
                v = (kv < 32) ? __ldg(&((const float4*)x0)[(size_t)gr * 32 + kv])
                              : __ldg(&((const float4*)x1)[(size_t)gr * 32 + (kv - 32)]);
            } else {
                v = __ldg(&((const float4*)x0)[(size_t)gr * 32 + kv]);
            }
        }
        *(float4*)&sX[r * XS + kv * 4] = v;
    }

    for (int p = 0; p < npass; ++p) {
        const float* W1 = p ? W1b : W1a;
        const float* b1 = p ? b1b : b1a;
        const float* W2 = p ? W2b : W2a;
        const float* b2 = p ? b2b : b2a;
        float*      out = p ? outB : outA;

        // ================= layer 1: h = relu(x @ W1 + b1) =================
        float acc[4][8];
        #pragma unroll
        for (int r = 0; r < 4; ++r)
            #pragma unroll
            for (int c = 0; c < 8; ++c) acc[r][c] = 0.f;

        for (int kc = 0; kc < KIN; kc += 128) {
            __syncthreads();  // sW free (prev use done)
            for (int i = tid; i < 128 * 32; i += 256) {
                const int k  = i >> 5;
                const int jv = i & 31;
                *(float4*)&sW[k * 128 + jv * 4] =
                    __ldg(&((const float4*)W1)[(size_t)(kc + k) * 32 + jv]);
            }
            __syncthreads();

            const float* xr0 = &sX[(ty * 4 + 0) * XS + kc];
            const float* xr1 = &sX[(ty * 4 + 1) * XS + kc];
            const float* xr2 = &sX[(ty * 4 + 2) * XS + kc];
            const float* xr3 = &sX[(ty * 4 + 3) * XS + kc];

            #pragma unroll 4
            for (int k = 0; k < 128; ++k) {
                const float4 w0 = *(const float4*)&sW[k * 128 + tx * 8];
                const float4 w1 = *(const float4*)&sW[k * 128 + tx * 8 + 4];
                const float wv[8] = {w0.x, w0.y, w0.z, w0.w, w1.x, w1.y, w1.z, w1.w};
                const float xv[4] = {xr0[k], xr1[k], xr2[k], xr3[k]};
                #pragma unroll
                for (int r = 0; r < 4; ++r)
                    #pragma unroll
                    for (int c = 0; c < 8; ++c)
                        acc[r][c] = fmaf(xv[r], wv[c], acc[r][c]);
            }
        }

        {   // bias + relu -> sH
            const float4 bb0 = __ldg(&((const float4*)b1)[tx * 2]);
            const float4 bb1 = __ldg(&((const float4*)b1)[tx * 2 + 1]);
            const float bv[8] = {bb0.x, bb0.y, bb0.z, bb0.w, bb1.x, bb1.y, bb1.z, bb1.w};
            #pragma unroll
            for (int r = 0; r < 4; ++r) {
                float4 h0, h1;
                h0.x = fmaxf(acc[r][0] + bv[0], 0.f);
                h0.y = fmaxf(acc[r][1] + bv[1], 0.f);
                h0.z = fmaxf(acc[r][2] + bv[2], 0.f);
                h0.w = fmaxf(acc[r][3] + bv[3], 0.f);
                h1.x = fmaxf(acc[r][4] + bv[4], 0.f);
                h1.y = fmaxf(acc[r][5] + bv[5], 0.f);
                h1.z = fmaxf(acc[r][6] + bv[6], 0.f);
                h1.w = fmaxf(acc[r][7] + bv[7], 0.f);
                *(float4*)&sH[(ty * 4 + r) * HS + tx * 8]     = h0;
                *(float4*)&sH[(ty * 4 + r) * HS + tx * 8 + 4] = h1;
            }
        }

        // ================= layer 2: out = relu(h @ W2 + b2) ===============
        __syncthreads();  // sH written, sW free
        for (int i = tid; i < 128 * 32; i += 256) {
            const int k  = i >> 5;
            const int jv = i & 31;
            *(float4*)&sW[k * 128 + jv * 4] =
                __ldg(&((const float4*)W2)[(size_t)k * 32 + jv]);
        }
        __syncthreads();

        float acc2[4][8];
        #pragma unroll
        for (int r = 0; r < 4; ++r)
            #pragma unroll
            for (int c = 0; c < 8; ++c) acc2[r][c] = 0.f;

        {
            const float* hr0 = &sH[(ty * 4 + 0) * HS];
            const float* hr1 = &sH[(ty * 4 + 1) * HS];
            const float* hr2 = &sH[(ty * 4 + 2) * HS];
            const float* hr3 = &sH[(ty * 4 + 3) * HS];
            #pragma unroll 4
            for (int k = 0; k < 128; ++k) {
                const float4 w0 = *(const float4*)&sW[k * 128 + tx * 8];
                const float4 w1 = *(const float4*)&sW[k * 128 + tx * 8 + 4];
                const float wv[8] = {w0.x, w0.y, w0.z, w0.w, w1.x, w1.y, w1.z, w1.w};
                const float xv[4] = {hr0[k], hr1[k], hr2[k], hr3[k]};
                #pragma unroll
                for (int r = 0; r < 4; ++r)
                    #pragma unroll
                    for (int c = 0; c < 8; ++c)
                        acc2[r][c] = fmaf(xv[r], wv[c], acc2[r][c]);
            }
        }

        {   // bias + relu -> gmem
            const float4 cb0 = __ldg(&((const float4*)b2)[tx * 2]);
            const float4 cb1 = __ldg(&((const float4*)b2)[tx * 2 + 1]);
            const float bv[8] = {cb0.x, cb0.y, cb0.z, cb0.w, cb1.x, cb1.y, cb1.z, cb1.w};
            #pragma unroll
            for (int r = 0; r < 4; ++r) {
                const int gr = row0 + ty * 4 + r;
                if (gr < nrows) {
                    float4 o0, o1;
                    o0.x = fmaxf(acc2[r][0] + bv[0], 0.f);
                    o0.y = fmaxf(acc2[r][1] + bv[1], 0.f);
                    o0.z = fmaxf(acc2[r][2] + bv[2], 0.f);
                    o0.w = fmaxf(acc2[r][3] + bv[3], 0.f);
                    o1.x = fmaxf(acc2[r][4] + bv[4], 0.f);
                    o1.y = fmaxf(acc2[r][5] + bv[5], 0.f);
                    o1.z = fmaxf(acc2[r][6] + bv[6], 0.f);
                    o1.w = fmaxf(acc2[r][7] + bv[7], 0.f);
                    ((float4*)out)[(size_t)gr * 32 + tx * 2]     = o0;
                    ((float4*)out)[(size_t)gr * 32 + tx * 2 + 1] = o1;
                }
            }
        }
        // next pass re-syncs before touching sW; sH rewritten only after that
    }
}

// ---------------------------------------------------------------------------
// Edge scatter: dst[didx[e]] += src[sidx[e]]  (rows of 128 floats)
// 32 lanes per edge, one float4 per lane, vector reduction to L2.
// ---------------------------------------------------------------------------
__device__ __forceinline__ void red_add_v4(float* addr, float4 v) {
    asm volatile("red.global.add.v4.f32 [%0], {%1,%2,%3,%4};"
                 :: "l"(addr), "f"(v.x), "f"(v.y), "f"(v.z), "f"(v.w)
                 : "memory");
}

__global__ void scatter_add_kernel(const float* __restrict__ src,
                                   const int* __restrict__ sidx,
                                   const int* __restrict__ didx,
                                   float* __restrict__ dst, int nE)
{
    const int t = blockIdx.x * blockDim.x + threadIdx.x;
    const int e = t >> 5;
    if (e >= nE) return;
    const int lane = t & 31;
    const int s = __ldg(&sidx[e]);
    const int d = __ldg(&didx[e]);
    const float4 v = __ldg(&((const float4*)src)[(size_t)s * 32 + lane]);
    red_add_v4(dst + (size_t)d * 128 + lane * 4, v);
}

// ---------------------------------------------------------------------------
// Launch
// ---------------------------------------------------------------------------
extern "C" void kernel_launch(void* const* d_in, const int* in_sizes, int n_in,
                              void* d_out, int out_size)
{
    const float* hv = (const float*)d_in[0];
    const float* hc = (const float*)d_in[1];
    auto W = [&](int i) { return (const float*)d_in[i]; };
    const int* pos_v = (const int*)d_in[26];
    const int* pos_c = (const int*)d_in[27];
    const int* neg_v = (const int*)d_in[28];
    const int* neg_c = (const int*)d_in[29];

    const int NV = in_sizes[0] / D128;
    const int NC = in_sizes[1] / D128;
    const int EP = in_sizes[26];
    const int EN = in_sizes[28];

    float *tmpA, *tmpB, *tmpC, *tmpD, *mv, *mc;
    cudaGetSymbolAddress((void**)&tmpA, g_tmpA);
    cudaGetSymbolAddress((void**)&tmpB, g_tmpB);
    cudaGetSymbolAddress((void**)&tmpC, g_tmpC);
    cudaGetSymbolAddress((void**)&tmpD, g_tmpD);
    cudaGetSymbolAddress((void**)&mv,   g_mv);
    cudaGetSymbolAddress((void**)&mc,   g_mc);

    constexpr int SMEM128 = (TM * (128 + 4) + TM * 132 + 128 * 128) * 4;  // 133120
    constexpr int SMEM256 = (TM * (256 + 4) + TM * 132 + 128 * 128) * 4;  // 165888
    cudaFuncSetAttribute(mlp2_kernel<128>,
                         cudaFuncAttributeMaxDynamicSharedMemorySize, SMEM128);
    cudaFuncSetAttribute(mlp2_kernel<256>,
                         cudaFuncAttributeMaxDynamicSharedMemorySize, SMEM256);

    // zero accumulators (captured as memset nodes)
    cudaMemsetAsync(mv, 0, (size_t)NV * D128 * sizeof(float), 0);
    cudaMemsetAsync(mc, 0, (size_t)NC * D128 * sizeof(float), 0);

    const int gc = (NC + TM - 1) / TM;
    const int gv = (NV + TM - 1) / TM;

    // message MLPs (pos+neg pair share the x tile)
    mlp2_kernel<128><<<gc, 256, SMEM128>>>(hc, nullptr,
        W(2), W(3), W(4), W(5), tmpA,
        W(6), W(7), W(8), W(9), tmpB, NC, 2);
    mlp2_kernel<128><<<gv, 256, SMEM128>>>(hv, nullptr,
        W(10), W(11), W(12), W(13), tmpC,
        W(14), W(15), W(16), W(17), tmpD, NV, 2);

    // edge segment-sums
    {
        const int tpe = 32;
        int bl;
        bl = (EP * tpe + 255) / 256;
        scatter_add_kernel<<<bl, 256>>>(tmpA, pos_c, pos_v, mv, EP);
        bl = (EN * tpe + 255) / 256;
        scatter_add_kernel<<<bl, 256>>>(tmpB, neg_c, neg_v, mv, EN);
        bl = (EP * tpe + 255) / 256;
        scatter_add_kernel<<<bl, 256>>>(tmpC, pos_v, pos_c, mc, EP);
        bl = (EN * tpe + 255) / 256;
        scatter_add_kernel<<<bl, 256>>>(tmpD, neg_v, neg_c, mc, EN);
    }

    // update MLPs on concat([h, m])
    float* out_v = (float*)d_out;
    float* out_c = (float*)d_out + (size_t)NV * D128;
    mlp2_kernel<256><<<gv, 256, SMEM256>>>(hv, mv,
        W(18), W(19), W(20), W(21), out_v,
        W(18), W(19), W(20), W(21), out_v, NV, 1);
    mlp2_kernel<256><<<gc, 256, SMEM256>>>(hc, mc,
        W(22), W(23), W(24), W(25), out_c,
        W(22), W(23), W(24), W(25), out_c, NC, 1);
}

// round 3
// speedup vs baseline: 3.1350x; 3.1350x over previous
#include <cuda_runtime.h>
#include <cstdint>
#include <cstddef>

// ---------------------------------------------------------------------------
// GraphConv bipartite GNN layer — tf32 tensor-core version (mma.sync.m16n8k8).
//   mv = seg_sum(fmv_pos(hc)[pos_c] -> pos_v) + seg_sum(fmv_neg(hc)[neg_c] -> neg_v)
//   mc = seg_sum(fmc_pos(hv)[pos_v] -> pos_c) + seg_sum(fmc_neg(hv)[neg_v] -> neg_c)
//   hv_out = mlp2([hv|mv], fuv)   hc_out = mlp2([hc|mc], fuc)
//
// Weights are pre-transposed (n-major) and pre-rounded to tf32 by small setup
// kernels so the GEMM kernel feeds both operands via ldmatrix.x4.b16 (fp32
// elements viewed as b16 pairs map exactly onto the tf32 mma fragments).
// ---------------------------------------------------------------------------

#define D128 128
#define NV_MAX 100000
#define NC_MAX 400000

// Scratch (static __device__ arrays per allocation rules)
__device__ float g_tmpA[(size_t)NC_MAX * D128];  // fmv_pos(hc)
__device__ float g_tmpB[(size_t)NC_MAX * D128];  // fmv_neg(hc)
__device__ float g_tmpC[(size_t)NV_MAX * D128];  // fmc_pos(hv)
__device__ float g_tmpD[(size_t)NV_MAX * D128];  // fmc_neg(hv)
__device__ float g_mv[(size_t)NV_MAX * D128];
__device__ float g_mc[(size_t)NC_MAX * D128];
// Transposed tf32 weights: 8x(128x128) + 2x(128x256 + 128x128)
__device__ float g_wt[229376];

// ---------------------------------------------------------------------------
// helpers
// ---------------------------------------------------------------------------
__device__ __forceinline__ uint32_t f2tf32(float x) {
    uint32_t r;
    asm("cvt.rna.tf32.f32 %0, %1;" : "=r"(r) : "f"(x));
    return r;
}

__device__ __forceinline__ void ldsm_x4(uint32_t (&r)[4], uint32_t addr) {
    asm volatile("ldmatrix.sync.aligned.m8n8.x4.shared.b16 {%0,%1,%2,%3}, [%4];"
                 : "=r"(r[0]), "=r"(r[1]), "=r"(r[2]), "=r"(r[3]) : "r"(addr));
}

__device__ __forceinline__ void mma_tf32(float (&c)[4], const uint32_t (&a)[4],
                                         uint32_t b0, uint32_t b1) {
    asm volatile(
        "mma.sync.aligned.m16n8k8.row.col.f32.tf32.tf32.f32 "
        "{%0,%1,%2,%3}, {%4,%5,%6,%7}, {%8,%9}, {%0,%1,%2,%3};"
        : "+f"(c[0]), "+f"(c[1]), "+f"(c[2]), "+f"(c[3])
        : "r"(a[0]), "r"(a[1]), "r"(a[2]), "r"(a[3]), "r"(b0), "r"(b1));
}

// ---------------------------------------------------------------------------
// Setup: Wt[n][k] = tf32(W[k][n]); N fixed at 128 columns of W.
// ---------------------------------------------------------------------------
__global__ void transpose_tf32_kernel(const float* __restrict__ W,
                                      float* __restrict__ Wt, int K) {
    __shared__ float t[32][33];
    const int kb = blockIdx.x * 32, nb = blockIdx.y * 32;
    const int tx = threadIdx.x, ty = threadIdx.y;  // 32 x 8
    for (int j = ty; j < 32; j += 8)
        t[j][tx] = __ldg(&W[(size_t)(kb + j) * 128 + nb + tx]);
    __syncthreads();
    for (int j = ty; j < 32; j += 8)
        ((uint32_t*)Wt)[(size_t)(nb + j) * K + kb + tx] = f2tf32(t[tx][j]);
}

// ---------------------------------------------------------------------------
// Fused 2-layer MLP on tensor cores.
// CTA: 128 rows x 128 cols, 256 threads = 8 warps (4x2), warp tile 32x64.
// KIN = 128 (x = x0) or 256 (x = [x0|x1]). npass = 2 reuses the staged x tile
// for a second weight set (pos/neg message MLP pair).
// Smem: sX[128][132], sW[128][132], sH[128][132]  (all tf32-in-fp32-bits).
// ---------------------------------------------------------------------------
#define SSTR 132

template <int KIN>
__global__ void __launch_bounds__(256, 1)
mlp2_tc(const float* __restrict__ x0, const float* __restrict__ x1,
        const float* __restrict__ W1ta, const float* __restrict__ b1a,
        const float* __restrict__ W2ta, const float* __restrict__ b2a,
        float* __restrict__ outA,
        const float* __restrict__ W1tb, const float* __restrict__ b1b,
        const float* __restrict__ W2tb, const float* __restrict__ b2b,
        float* __restrict__ outB,
        int nrows, int npass)
{
    extern __shared__ float smem[];
    float* sX = smem;                 // 128 * SSTR
    float* sW = sX + 128 * SSTR;
    float* sH = sW + 128 * SSTR;
    const uint32_t sXa = (uint32_t)__cvta_generic_to_shared(sX);
    const uint32_t sWa = (uint32_t)__cvta_generic_to_shared(sW);
    const uint32_t sHa = (uint32_t)__cvta_generic_to_shared(sH);

    const int tid  = threadIdx.x;
    const int lane = tid & 31;
    const int wid  = tid >> 5;
    const int wm   = wid >> 1;   // 0..3 : 32-row band
    const int wn   = wid & 1;    // 0..1 : 64-col half
    const int row0 = blockIdx.x * 128;

    // per-thread ldmatrix address pieces: row = (lane&15), col half = (lane>>4)*4
    const int lrow = lane & 15;
    const int lcol = (lane >> 4) << 2;

    // ---- staging lambdas ----
    auto stage_x = [&](int ch) {
        const float* src = (KIN == 256 && ch == 1) ? x1 : x0;
        for (int i = tid; i < 128 * 32; i += 256) {
            const int r = i >> 5, c = i & 31;
            const int gr = row0 + r;
            float4 v = make_float4(0.f, 0.f, 0.f, 0.f);
            if (gr < nrows) v = __ldg(&((const float4*)src)[(size_t)gr * 32 + c]);
            uint4 t;
            t.x = f2tf32(v.x); t.y = f2tf32(v.y);
            t.z = f2tf32(v.z); t.w = f2tf32(v.w);
            *(uint4*)&sX[r * SSTR + c * 4] = t;
        }
    };
    auto stage_w = [&](const float* Wt, int ktot, int ch) {
        for (int i = tid; i < 128 * 32; i += 256) {
            const int n = i >> 5, c = i & 31;
            float4 v = __ldg(&((const float4*)(Wt + (size_t)n * ktot + ch * 128))[c]);
            *(float4*)&sW[n * SSTR + c * 4] = v;
        }
    };

    // ---- GEMM over one 128-K chunk: acc += A(128x128) * Wt^T ----
    auto gemm128 = [&](uint32_t Aa, float (&acc)[2][8][4]) {
        #pragma unroll 4
        for (int ks = 0; ks < 16; ++ks) {
            const int k0 = ks * 8;
            uint32_t a[2][4];
            #pragma unroll
            for (int mi = 0; mi < 2; ++mi) {
                uint32_t addr = Aa + 4u * ((wm * 32 + mi * 16 + lrow) * SSTR + k0 + lcol);
                ldsm_x4(a[mi], addr);
            }
            uint32_t b[4][4];
            #pragma unroll
            for (int ni = 0; ni < 4; ++ni) {
                uint32_t addr = sWa + 4u * ((wn * 64 + ni * 16 + lrow) * SSTR + k0 + lcol);
                ldsm_x4(b[ni], addr);
            }
            #pragma unroll
            for (int mi = 0; mi < 2; ++mi)
                #pragma unroll
                for (int ni = 0; ni < 4; ++ni) {
                    mma_tf32(acc[mi][2 * ni],     a[mi], b[ni][0], b[ni][2]);
                    mma_tf32(acc[mi][2 * ni + 1], a[mi], b[ni][1], b[ni][3]);
                }
        }
    };

    for (int p = 0; p < npass; ++p) {
        const float* W1t = p ? W1tb : W1ta;
        const float* b1  = p ? b1b  : b1a;
        const float* W2t = p ? W2tb : W2ta;
        const float* b2  = p ? b2b  : b2a;
        float*       out = p ? outB : outA;

        // ================= layer 1 =================
        float acc[2][8][4];
        #pragma unroll
        for (int mi = 0; mi < 2; ++mi)
            #pragma unroll
            for (int nj = 0; nj < 8; ++nj)
                #pragma unroll
                for (int r = 0; r < 4; ++r) acc[mi][nj][r] = 0.f;

        #pragma unroll
        for (int ch = 0; ch < KIN / 128; ++ch) {
            __syncthreads();                       // buffers free
            if (!(KIN == 128 && p == 1)) stage_x(ch);
            stage_w(W1t, KIN, ch);
            __syncthreads();
            gemm128(sXa, acc);
        }

        __syncthreads();                           // all reads of sX/sW done
        // bias + relu -> sH (tf32), and stage W2t
        #pragma unroll
        for (int mi = 0; mi < 2; ++mi)
            #pragma unroll
            for (int nj = 0; nj < 8; ++nj) {
                const int colb = wn * 64 + (nj >> 1) * 16 + (nj & 1) * 8 + 2 * (lane & 3);
                const float bx = __ldg(&b1[colb]);
                const float by = __ldg(&b1[colb + 1]);
                const int ra = wm * 32 + mi * 16 + (lane >> 2);
                uint2 u0, u1;
                u0.x = f2tf32(fmaxf(acc[mi][nj][0] + bx, 0.f));
                u0.y = f2tf32(fmaxf(acc[mi][nj][1] + by, 0.f));
                u1.x = f2tf32(fmaxf(acc[mi][nj][2] + bx, 0.f));
                u1.y = f2tf32(fmaxf(acc[mi][nj][3] + by, 0.f));
                *(uint2*)&sH[ra * SSTR + colb]       = u0;
                *(uint2*)&sH[(ra + 8) * SSTR + colb] = u1;
            }
        stage_w(W2t, 128, 0);
        __syncthreads();

        // ================= layer 2 =================
        #pragma unroll
        for (int mi = 0; mi < 2; ++mi)
            #pragma unroll
            for (int nj = 0; nj < 8; ++nj)
                #pragma unroll
                for (int r = 0; r < 4; ++r) acc[mi][nj][r] = 0.f;
        gemm128(sHa, acc);

        // bias + relu -> gmem (fp32)
        #pragma unroll
        for (int mi = 0; mi < 2; ++mi)
            #pragma unroll
            for (int nj = 0; nj < 8; ++nj) {
                const int colb = wn * 64 + (nj >> 1) * 16 + (nj & 1) * 8 + 2 * (lane & 3);
                const float bx = __ldg(&b2[colb]);
                const float by = __ldg(&b2[colb + 1]);
                const int r0 = row0 + wm * 32 + mi * 16 + (lane >> 2);
                if (r0 < nrows) {
                    float2 v;
                    v.x = fmaxf(acc[mi][nj][0] + bx, 0.f);
                    v.y = fmaxf(acc[mi][nj][1] + by, 0.f);
                    *(float2*)&out[(size_t)r0 * 128 + colb] = v;
                }
                if (r0 + 8 < nrows) {
                    float2 v;
                    v.x = fmaxf(acc[mi][nj][2] + bx, 0.f);
                    v.y = fmaxf(acc[mi][nj][3] + by, 0.f);
                    *(float2*)&out[(size_t)(r0 + 8) * 128 + colb] = v;
                }
            }
        // next pass begins with __syncthreads() before restaging sW
    }
}

// ---------------------------------------------------------------------------
// Edge scatter: dst[didx[e]] += src[sidx[e]]  (rows of 128 floats)
// ---------------------------------------------------------------------------
__device__ __forceinline__ void red_add_v4(float* addr, float4 v) {
    asm volatile("red.global.add.v4.f32 [%0], {%1,%2,%3,%4};"
                 :: "l"(addr), "f"(v.x), "f"(v.y), "f"(v.z), "f"(v.w)
                 : "memory");
}

__global__ void scatter_add_kernel(const float* __restrict__ src,
                                   const int* __restrict__ sidx,
                                   const int* __restrict__ didx,
                                   float* __restrict__ dst, int nE)
{
    const int t = blockIdx.x * blockDim.x + threadIdx.x;
    const int e = t >> 5;
    if (e >= nE) return;
    const int lane = t & 31;
    const int s = __ldg(&sidx[e]);
    const int d = __ldg(&didx[e]);
    const float4 v = __ldg(&((const float4*)src)[(size_t)s * 32 + lane]);
    red_add_v4(dst + (size_t)d * 128 + lane * 4, v);
}

// ---------------------------------------------------------------------------
// Launch
// ---------------------------------------------------------------------------
extern "C" void kernel_launch(void* const* d_in, const int* in_sizes, int n_in,
                              void* d_out, int out_size)
{
    const float* hv = (const float*)d_in[0];
    const float* hc = (const float*)d_in[1];
    auto W = [&](int i) { return (const float*)d_in[i]; };
    const int* pos_v = (const int*)d_in[26];
    const int* pos_c = (const int*)d_in[27];
    const int* neg_v = (const int*)d_in[28];
    const int* neg_c = (const int*)d_in[29];

    const int NV = in_sizes[0] / D128;
    const int NC = in_sizes[1] / D128;
    const int EP = in_sizes[26];
    const int EN = in_sizes[28];

    float *tmpA, *tmpB, *tmpC, *tmpD, *mv, *mc, *wt;
    cudaGetSymbolAddress((void**)&tmpA, g_tmpA);
    cudaGetSymbolAddress((void**)&tmpB, g_tmpB);
    cudaGetSymbolAddress((void**)&tmpC, g_tmpC);
    cudaGetSymbolAddress((void**)&tmpD, g_tmpD);
    cudaGetSymbolAddress((void**)&mv,   g_mv);
    cudaGetSymbolAddress((void**)&mc,   g_mc);
    cudaGetSymbolAddress((void**)&wt,   g_wt);

    // transposed-weight scratch offsets
    float* fmvp_W1t = wt;            float* fmvp_W2t = wt + 16384;
    float* fmvn_W1t = wt + 32768;    float* fmvn_W2t = wt + 49152;
    float* fmcp_W1t = wt + 65536;    float* fmcp_W2t = wt + 81920;
    float* fmcn_W1t = wt + 98304;    float* fmcn_W2t = wt + 114688;
    float* fuv_W1t  = wt + 131072;   float* fuv_W2t  = wt + 163840;
    float* fuc_W1t  = wt + 180224;   float* fuc_W2t  = wt + 212992;

    // setup: transpose + tf32-round all weights
    auto T = [&](const float* Wsrc, float* Wdst, int K) {
        transpose_tf32_kernel<<<dim3(K / 32, 4), dim3(32, 8)>>>(Wsrc, Wdst, K);
    };
    T(W(2),  fmvp_W1t, 128);  T(W(4),  fmvp_W2t, 128);
    T(W(6),  fmvn_W1t, 128);  T(W(8),  fmvn_W2t, 128);
    T(W(10), fmcp_W1t, 128);  T(W(12), fmcp_W2t, 128);
    T(W(14), fmcn_W1t, 128);  T(W(16), fmcn_W2t, 128);
    T(W(18), fuv_W1t,  256);  T(W(20), fuv_W2t,  128);
    T(W(22), fuc_W1t,  256);  T(W(24), fuc_W2t,  128);

    constexpr int SMEM = 3 * 128 * SSTR * 4;  // 202752 bytes
    cudaFuncSetAttribute(mlp2_tc<128>,
                         cudaFuncAttributeMaxDynamicSharedMemorySize, SMEM);
    cudaFuncSetAttribute(mlp2_tc<256>,
                         cudaFuncAttributeMaxDynamicSharedMemorySize, SMEM);

    // zero accumulators
    cudaMemsetAsync(mv, 0, (size_t)NV * D128 * sizeof(float), 0);
    cudaMemsetAsync(mc, 0, (size_t)NC * D128 * sizeof(float), 0);

    const int gc = (NC + 127) / 128;
    const int gv = (NV + 127) / 128;

    // message MLPs (pos+neg share the staged x tile)
    mlp2_tc<128><<<gc, 256, SMEM>>>(hc, nullptr,
        fmvp_W1t, W(3), fmvp_W2t, W(5), tmpA,
        fmvn_W1t, W(7), fmvn_W2t, W(9), tmpB, NC, 2);
    mlp2_tc<128><<<gv, 256, SMEM>>>(hv, nullptr,
        fmcp_W1t, W(11), fmcp_W2t, W(13), tmpC,
        fmcn_W1t, W(15), fmcn_W2t, W(17), tmpD, NV, 2);

    // edge segment-sums
    {
        int bl;
        bl = (EP * 32 + 255) / 256;
        scatter_add_kernel<<<bl, 256>>>(tmpA, pos_c, pos_v, mv, EP);
        bl = (EN * 32 + 255) / 256;
        scatter_add_kernel<<<bl, 256>>>(tmpB, neg_c, neg_v, mv, EN);
        bl = (EP * 32 + 255) / 256;
        scatter_add_kernel<<<bl, 256>>>(tmpC, pos_v, pos_c, mc, EP);
        bl = (EN * 32 + 255) / 256;
        scatter_add_kernel<<<bl, 256>>>(tmpD, neg_v, neg_c, mc, EN);
    }

    // update MLPs on concat([h, m])
    float* out_v = (float*)d_out;
    float* out_c = (float*)d_out + (size_t)NV * D128;
    mlp2_tc<256><<<gv, 256, SMEM>>>(hv, mv,
        fuv_W1t, W(19), fuv_W2t, W(21), out_v,
        fuv_W1t, W(19), fuv_W2t, W(21), out_v, NV, 1);
    mlp2_tc<256><<<gc, 256, SMEM>>>(hc, mc,
        fuc_W1t, W(23), fuc_W2t, W(25), out_c,
        fuc_W1t, W(23), fuc_W2t, W(25), out_c, NC, 1);
}